// round 5
// baseline (speedup 1.0000x reference)
#include <cuda_runtime.h>
#include <cstdint>

#define BT 2048
#define HS 1024
#define HT 2048
#define VSZ 32000
#define IGNORE_INDEX (-100)

// ---------------- scratch (static device arrays: allocation-guard safe) -----
__device__ float g_slog[(size_t)BT * VSZ];   // student logits
__device__ float g_tlog[(size_t)BT * VSZ];   // teacher logits
__device__ float g_lse_s[BT];
__device__ float g_lse_t[BT];
__device__ float g_per_token[BT];

// ---------------- GEMM: C[t,v] = sum_h A[t,h] * B[v,h] ---------------------
// A: (BT x K) row-major, B: (VSZ x K) row-major. Both K-contiguous -> coalesced.
// 128x128x16 block tile, 256 threads, 8x8 per-thread microtile computed as
// 8x4 packed f32x2 accumulators via fma.rn.f32x2 (FFMA2, sm_103a).
#define BM 128
#define BN 128
#define BK 16

__global__ __launch_bounds__(256, 2)
void gemm_kernel(const float* __restrict__ A, const float* __restrict__ B,
                 int K, int student)
{
    __shared__ float As2[BK][2 * BM];   // A duplicated: As2[k][2m]=As2[k][2m+1]=A
    __shared__ float Bs[BK][BN];

    const int tid = threadIdx.x;
    const int m0 = blockIdx.y * BM;
    const int n0 = blockIdx.x * BN;
    const int ty8 = (tid >> 4) * 8;     // 0..120 step 8 (m within tile)
    const int tx8 = (tid & 15) * 8;     // 0..120 step 8 (n within tile)

    unsigned long long acc[8][4];
#pragma unroll
    for (int i = 0; i < 8; i++)
#pragma unroll
        for (int j = 0; j < 4; j++) acc[i][j] = 0ull;

    const int lrow = tid >> 2;          // 0..63
    const int lc4  = (tid & 3) * 4;     // 0,4,8,12

    for (int k0 = 0; k0 < K; k0 += BK) {
        // ---- load tiles ----
#pragma unroll
        for (int p = 0; p < 2; p++) {
            const int row = lrow + p * 64;
            float4 av = *(const float4*)(A + (size_t)(m0 + row) * K + k0 + lc4);
            As2[lc4 + 0][2 * row] = av.x; As2[lc4 + 0][2 * row + 1] = av.x;
            As2[lc4 + 1][2 * row] = av.y; As2[lc4 + 1][2 * row + 1] = av.y;
            As2[lc4 + 2][2 * row] = av.z; As2[lc4 + 2][2 * row + 1] = av.z;
            As2[lc4 + 3][2 * row] = av.w; As2[lc4 + 3][2 * row + 1] = av.w;
            float4 bv = *(const float4*)(B + (size_t)(n0 + row) * K + k0 + lc4);
            Bs[lc4 + 0][row] = bv.x;
            Bs[lc4 + 1][row] = bv.y;
            Bs[lc4 + 2][row] = bv.z;
            Bs[lc4 + 3][row] = bv.w;
        }
        __syncthreads();

        // ---- compute ----
#pragma unroll
        for (int k = 0; k < BK; k++) {
            unsigned long long areg[8], breg[4];
#pragma unroll
            for (int i = 0; i < 8; i++)
                areg[i] = *(const unsigned long long*)&As2[k][2 * (ty8 + i)];
#pragma unroll
            for (int j = 0; j < 4; j++)
                breg[j] = *(const unsigned long long*)&Bs[k][tx8 + 2 * j];
#pragma unroll
            for (int i = 0; i < 8; i++)
#pragma unroll
                for (int j = 0; j < 4; j++)
                    asm("fma.rn.f32x2 %0, %1, %2, %0;"
                        : "+l"(acc[i][j]) : "l"(areg[i]), "l"(breg[j]));
        }
        __syncthreads();
    }

    float* __restrict__ C = student ? g_slog : g_tlog;
#pragma unroll
    for (int i = 0; i < 8; i++) {
        const size_t base = (size_t)(m0 + ty8 + i) * VSZ + n0 + tx8;
#pragma unroll
        for (int j = 0; j < 4; j++)
            *(unsigned long long*)(C + base + 2 * j) = acc[i][j];
    }
}

// ---------------- per-row log-sum-exp --------------------------------------
__global__ __launch_bounds__(256)
void rowstats_kernel(int student)
{
    const float* __restrict__ x =
        (student ? g_slog : g_tlog) + (size_t)blockIdx.x * VSZ;
    const float4* __restrict__ x4 = (const float4*)x;
    const int n4 = VSZ / 4;   // 8000
    const int tid = threadIdx.x;

    __shared__ float red[256];

    float m = -1e30f;
    for (int i = tid; i < n4; i += 256) {
        float4 v = x4[i];
        m = fmaxf(m, fmaxf(fmaxf(v.x, v.y), fmaxf(v.z, v.w)));
    }
    red[tid] = m;
    __syncthreads();
    for (int s = 128; s > 0; s >>= 1) {
        if (tid < s) red[tid] = fmaxf(red[tid], red[tid + s]);
        __syncthreads();
    }
    m = red[0];
    __syncthreads();

    float ssum = 0.f;
    for (int i = tid; i < n4; i += 256) {
        float4 v = x4[i];
        ssum += __expf(v.x - m) + __expf(v.y - m)
              + __expf(v.z - m) + __expf(v.w - m);
    }
    red[tid] = ssum;
    __syncthreads();
    for (int s = 128; s > 0; s >>= 1) {
        if (tid < s) red[tid] += red[tid + s];
        __syncthreads();
    }
    if (tid == 0) {
        float* lse = student ? g_lse_s : g_lse_t;
        lse[blockIdx.x] = m + __logf(red[0]);
    }
}

// ---------------- per-row JSD ----------------------------------------------
__global__ __launch_bounds__(256)
void jsd_kernel()
{
    const int row = blockIdx.x;
    const int tid = threadIdx.x;
    const size_t base = (size_t)row * VSZ;
    const float4* __restrict__ s4 = (const float4*)(g_slog + base);
    const float4* __restrict__ t4 = (const float4*)(g_tlog + base);
    const float lse_s = g_lse_s[row];
    const float lse_t = g_lse_t[row];
    const int n4 = VSZ / 4;

    float acc = 0.f;
    for (int i = tid; i < n4; i += 256) {
        float4 sv = s4[i];
        float4 tv = t4[i];
        float sl[4] = {sv.x, sv.y, sv.z, sv.w};
        float tl[4] = {tv.x, tv.y, tv.z, tv.w};
#pragma unroll
        for (int e = 0; e < 4; e++) {
            float lq = sl[e] - lse_s;
            float lp = tl[e] - lse_t;
            float q = __expf(lq);
            float p = __expf(lp);
            float mm = 0.5f * (p + q);
            float lm = __logf(mm);
            acc += 0.5f * (p * (lp - lm) + q * (lq - lm));
        }
    }

    __shared__ float red[256];
    red[tid] = acc;
    __syncthreads();
    for (int s = 128; s > 0; s >>= 1) {
        if (tid < s) red[tid] += red[tid + s];
        __syncthreads();
    }
    if (tid == 0) g_per_token[row] = red[0];
}

// ---------------- final masked mean ----------------------------------------
__global__ __launch_bounds__(1024)
void final_kernel(const int* __restrict__ label, float* __restrict__ out)
{
    const int tid = threadIdx.x;
    float sum = 0.f;
    int cnt = 0;
    for (int i = tid; i < BT; i += 1024) {
        if (label[i] != IGNORE_INDEX) {
            sum += g_per_token[i];
            cnt++;
        }
    }
    __shared__ float rs[1024];
    __shared__ int rc[1024];
    rs[tid] = sum; rc[tid] = cnt;
    __syncthreads();
    for (int s = 512; s > 0; s >>= 1) {
        if (tid < s) { rs[tid] += rs[tid + s]; rc[tid] += rc[tid + s]; }
        __syncthreads();
    }
    if (tid == 0) {
        int n = rc[0] > 1 ? rc[0] : 1;
        out[0] = rs[0] / (float)n;
    }
}

// ---------------- launch ----------------------------------------------------
extern "C" void kernel_launch(void* const* d_in, const int* in_sizes, int n_in,
                              void* d_out, int out_size)
{
    const float* s_in = (const float*)d_in[0];   // (BT, HS)
    const float* s_w  = (const float*)d_in[1];   // (VSZ, HS)
    const float* t_in = (const float*)d_in[2];   // (BT, HT)
    const float* t_w  = (const float*)d_in[3];   // (VSZ, HT)
    const int*   lab  = (const int*)d_in[4];     // (BT,)
    float* out = (float*)d_out;

    dim3 grid(VSZ / BN, BT / BM);                // (250, 16)
    gemm_kernel<<<grid, 256>>>(s_in, s_w, HS, 1);
    gemm_kernel<<<grid, 256>>>(t_in, t_w, HT, 0);
    rowstats_kernel<<<BT, 256>>>(1);
    rowstats_kernel<<<BT, 256>>>(0);
    jsd_kernel<<<BT, 256>>>();
    final_kernel<<<1, 1024>>>(lab, out);
}

// round 12
// speedup vs baseline: 3.2376x; 3.2376x over previous
#include <cuda_runtime.h>
#include <cuda_bf16.h>
#include <cstdint>

#define BT 2048
#define HS 1024
#define HT 2048
#define VSZ 32000
#define IGNORE_INDEX (-100)

// GEMM tiling
#define STAGES 4
#define APITCH 80                       // 64B row + 16B pad (16B aligned, bank-safe)
#define TILE_B (128 * APITCH)           // 10240 B per operand tile
#define STAGE_B (2 * TILE_B)            // 20480 B
#define SMEM_DYN (STAGES * STAGE_B)     // 81920 B

// ---------------- scratch (static device arrays: allocation-guard safe) -----
// NOTE: these symbols are ONLY referenced from device code. Taking their
// address in host code yields the host shadow (and GB300 ATS makes that a
// silent wrong-memory access instead of a crash).
__device__ float g_slog[(size_t)BT * VSZ];
__device__ float g_tlog[(size_t)BT * VSZ];
__device__ float g_lse_s[BT];
__device__ float g_lse_t[BT];
__device__ float g_per_token[BT];
// split-bf16 operands
__device__ __nv_bfloat16 g_As[(size_t)BT * 3 * HS];      // [hi|hi|lo]
__device__ __nv_bfloat16 g_At[(size_t)BT * 3 * HT];
__device__ __nv_bfloat16 g_Bs[(size_t)VSZ * 3 * HS];     // [hi|lo|hi]
__device__ __nv_bfloat16 g_Bt[(size_t)VSZ * 3 * HT];

// ---------------- PTX helpers ----------------------------------------------
__device__ __forceinline__ uint32_t smem_u32(const void* p) {
    uint32_t a;
    asm("{ .reg .u64 t; cvta.to.shared.u64 t, %1; cvt.u32.u64 %0, t; }" : "=r"(a) : "l"(p));
    return a;
}
#define CP_ASYNC16(dst, src) \
    asm volatile("cp.async.cg.shared.global [%0], [%1], 16;" :: "r"(dst), "l"(src))
#define CP_COMMIT() asm volatile("cp.async.commit_group;" ::: "memory")
#define CP_WAIT2()  asm volatile("cp.async.wait_group 2;" ::: "memory")

__device__ __forceinline__ void ldsm4(uint32_t* r, uint32_t addr) {
    asm volatile("ldmatrix.sync.aligned.m8n8.x4.shared.b16 {%0,%1,%2,%3}, [%4];"
        : "=r"(r[0]), "=r"(r[1]), "=r"(r[2]), "=r"(r[3]) : "r"(addr));
}
__device__ __forceinline__ void mma16816(float* c, const uint32_t* a,
                                         uint32_t b0, uint32_t b1) {
    asm volatile("mma.sync.aligned.m16n8k16.row.col.f32.bf16.bf16.f32 "
        "{%0,%1,%2,%3}, {%4,%5,%6,%7}, {%8,%9}, {%0,%1,%2,%3};"
        : "+f"(c[0]), "+f"(c[1]), "+f"(c[2]), "+f"(c[3])
        : "r"(a[0]), "r"(a[1]), "r"(a[2]), "r"(a[3]), "r"(b0), "r"(b1));
}

// ---------------- fp32 -> split bf16 conversion -----------------------------
// dsel: 0=g_As (K=HS, [hi|hi|lo])  1=g_At (K=HT, [hi|hi|lo])
//       2=g_Bs (K=HS, [hi|lo|hi])  3=g_Bt (K=HT, [hi|lo|hi])
__global__ __launch_bounds__(256)
void split_kernel(const float* __restrict__ src, int dsel, int K, long long n)
{
    __nv_bfloat16* dst;
    switch (dsel) {
        case 0: dst = g_As; break;
        case 1: dst = g_At; break;
        case 2: dst = g_Bs; break;
        default: dst = g_Bt; break;
    }
    const int bpat = (dsel >= 2);
    long long n4 = n >> 2;
    for (long long i4 = (long long)blockIdx.x * blockDim.x + threadIdx.x;
         i4 < n4; i4 += (long long)gridDim.x * blockDim.x) {
        long long idx = i4 * 4;
        int r = (int)(idx / K);
        int c = (int)(idx - (long long)r * K);
        float4 v = ((const float4*)src)[i4];
        float vv[4] = {v.x, v.y, v.z, v.w};
        unsigned long long hp = 0, lp = 0;
#pragma unroll
        for (int j = 0; j < 4; j++) {
            __nv_bfloat16 hb = __float2bfloat16(vv[j]);
            __nv_bfloat16 lb = __float2bfloat16(vv[j] - __bfloat162float(hb));
            hp |= (unsigned long long)__bfloat16_as_ushort(hb) << (16 * j);
            lp |= (unsigned long long)__bfloat16_as_ushort(lb) << (16 * j);
        }
        size_t rb = (size_t)r * 3 * K + c;
        *(unsigned long long*)(dst + rb)         = hp;
        *(unsigned long long*)(dst + rb + K)     = bpat ? lp : hp;
        *(unsigned long long*)(dst + rb + 2 * K) = bpat ? hp : lp;
    }
}

// ---------------- HMMA GEMM: C[m,n] = sum_k A'[m,k] B'[n,k] -----------------
// which=0: student (K'=3*HS), which=1: teacher (K'=3*HT). Pointers bound to
// device globals INSIDE device code.
// 128x128x32 CTA tile, 8 warps -> 64x32 per warp (4x4 m16n8k16 tiles).
__global__ __launch_bounds__(256, 2)
void gemm_tc_kernel(int which)
{
    const __nv_bfloat16* __restrict__ A = which ? g_At : g_As;
    const __nv_bfloat16* __restrict__ B = which ? g_Bt : g_Bs;
    float* __restrict__ C = which ? g_tlog : g_slog;
    const int nch = which ? (3 * HT / 32) : (3 * HS / 32);

    extern __shared__ char smem[];
    const uint32_t sb = smem_u32(smem);
    const int tid = threadIdx.x;
    const int wid = tid >> 5;
    const int lid = tid & 31;
    const int m0 = blockIdx.x * 128;
    const int n0 = blockIdx.y * 128;
    const int mw = (wid & 1) * 64;      // warp m offset in tile
    const int nw = (wid >> 1) * 32;     // warp n offset in tile
    const size_t rowb = (size_t)nch * 64;   // gmem row stride in bytes
    const char* Ab = (const char*)A;
    const char* Bb = (const char*)B;

    float acc[4][4][4];
#pragma unroll
    for (int i = 0; i < 4; i++)
#pragma unroll
        for (int j = 0; j < 4; j++)
#pragma unroll
            for (int e = 0; e < 4; e++) acc[i][j][e] = 0.f;

    // cp.async geometry: 512 granules (16B) per operand tile, 2 each per thread
    const int gr0 = tid >> 2;           // row 0..63
    const int gc0 = (tid & 3) * 16;     // 0..48

#define LOAD_CHUNK(cidx, stg) do {                                              \
        uint32_t sA_ = sb + (stg) * STAGE_B;                                    \
        uint32_t sB_ = sA_ + TILE_B;                                            \
        size_t ko_ = (size_t)(cidx) * 64;                                       \
        _Pragma("unroll")                                                       \
        for (int p_ = 0; p_ < 2; p_++) {                                        \
            int row_ = gr0 + p_ * 64;                                           \
            uint32_t so_ = (uint32_t)(row_ * APITCH + gc0);                     \
            CP_ASYNC16(sA_ + so_, Ab + (size_t)(m0 + row_) * rowb + ko_ + gc0); \
            CP_ASYNC16(sB_ + so_, Bb + (size_t)(n0 + row_) * rowb + ko_ + gc0); \
        }                                                                       \
    } while (0)

    // prologue: stages 0..2
#pragma unroll
    for (int c = 0; c < STAGES - 1; c++) { LOAD_CHUNK(c, c); CP_COMMIT(); }

    // per-thread ldmatrix base offsets (within a stage, k-step 0)
    const uint32_t a_base = (uint32_t)((mw + (lid & 15)) * APITCH
                                       + ((lid >> 4) & 1) * 16);
    const uint32_t b_base = (uint32_t)((nw + ((lid >> 4) & 1) * 8 + (lid & 7)) * APITCH
                                       + ((lid >> 3) & 1) * 16);

    for (int c = 0; c < nch; c++) {
        CP_WAIT2();                 // chunk c resident
        __syncthreads();            // all warps done with stage (c-1)%STAGES
        const int cn = c + STAGES - 1;
        if (cn < nch) LOAD_CHUNK(cn, cn % STAGES);
        CP_COMMIT();

        const uint32_t sA = sb + (c % STAGES) * STAGE_B;
        const uint32_t sB = sA + TILE_B;
#pragma unroll
        for (int s = 0; s < 2; s++) {   // two k16 steps per 32-K chunk
            uint32_t a[4][4], b[2][4];
#pragma unroll
            for (int mt = 0; mt < 4; mt++)
                ldsm4(a[mt], sA + a_base + mt * 16 * APITCH + s * 32);
#pragma unroll
            for (int np = 0; np < 2; np++)
                ldsm4(b[np], sB + b_base + np * 16 * APITCH + s * 32);
#pragma unroll
            for (int mt = 0; mt < 4; mt++)
#pragma unroll
                for (int nt = 0; nt < 4; nt++)
                    mma16816(acc[mt][nt], a[mt],
                             b[nt >> 1][(nt & 1) * 2], b[nt >> 1][(nt & 1) * 2 + 1]);
        }
    }

    // epilogue: direct fp32 stores
    const int r0 = m0 + mw + (lid >> 2);
    const int cc = n0 + nw + (lid & 3) * 2;
#pragma unroll
    for (int mt = 0; mt < 4; mt++) {
#pragma unroll
        for (int nt = 0; nt < 4; nt++) {
            float* p = C + (size_t)(r0 + mt * 16) * VSZ + cc + nt * 8;
            *(float2*)p = make_float2(acc[mt][nt][0], acc[mt][nt][1]);
            *(float2*)(p + 8 * (size_t)VSZ) = make_float2(acc[mt][nt][2], acc[mt][nt][3]);
        }
    }
#undef LOAD_CHUNK
}

// ---------------- per-row log-sum-exp --------------------------------------
__global__ __launch_bounds__(256)
void rowstats_kernel(int student)
{
    const float* __restrict__ x =
        (student ? g_slog : g_tlog) + (size_t)blockIdx.x * VSZ;
    const float4* __restrict__ x4 = (const float4*)x;
    const int n4 = VSZ / 4;
    const int tid = threadIdx.x;
    __shared__ float red[256];

    float m = -1e30f;
    for (int i = tid; i < n4; i += 256) {
        float4 v = x4[i];
        m = fmaxf(m, fmaxf(fmaxf(v.x, v.y), fmaxf(v.z, v.w)));
    }
    red[tid] = m;
    __syncthreads();
    for (int s = 128; s > 0; s >>= 1) {
        if (tid < s) red[tid] = fmaxf(red[tid], red[tid + s]);
        __syncthreads();
    }
    m = red[0];
    __syncthreads();

    float ssum = 0.f;
    for (int i = tid; i < n4; i += 256) {
        float4 v = x4[i];
        ssum += __expf(v.x - m) + __expf(v.y - m)
              + __expf(v.z - m) + __expf(v.w - m);
    }
    red[tid] = ssum;
    __syncthreads();
    for (int s = 128; s > 0; s >>= 1) {
        if (tid < s) red[tid] += red[tid + s];
        __syncthreads();
    }
    if (tid == 0) {
        float* lse = student ? g_lse_s : g_lse_t;
        lse[blockIdx.x] = m + __logf(red[0]);
    }
}

// ---------------- per-row JSD ----------------------------------------------
__global__ __launch_bounds__(256)
void jsd_kernel()
{
    const int row = blockIdx.x;
    const int tid = threadIdx.x;
    const size_t base = (size_t)row * VSZ;
    const float4* __restrict__ s4 = (const float4*)(g_slog + base);
    const float4* __restrict__ t4 = (const float4*)(g_tlog + base);
    const float lse_s = g_lse_s[row];
    const float lse_t = g_lse_t[row];
    const int n4 = VSZ / 4;

    float acc = 0.f;
    for (int i = tid; i < n4; i += 256) {
        float4 sv = s4[i];
        float4 tv = t4[i];
        float sl[4] = {sv.x, sv.y, sv.z, sv.w};
        float tl[4] = {tv.x, tv.y, tv.z, tv.w};
#pragma unroll
        for (int e = 0; e < 4; e++) {
            float lq = sl[e] - lse_s;
            float lp = tl[e] - lse_t;
            float q = __expf(lq);
            float p = __expf(lp);
            float mm = 0.5f * (p + q);
            float lm = __logf(mm);
            acc += 0.5f * (p * (lp - lm) + q * (lq - lm));
        }
    }

    __shared__ float red[256];
    red[tid] = acc;
    __syncthreads();
    for (int s = 128; s > 0; s >>= 1) {
        if (tid < s) red[tid] += red[tid + s];
        __syncthreads();
    }
    if (tid == 0) g_per_token[row] = red[0];
}

// ---------------- final masked mean ----------------------------------------
__global__ __launch_bounds__(1024)
void final_kernel(const int* __restrict__ label, float* __restrict__ out)
{
    const int tid = threadIdx.x;
    float sum = 0.f;
    int cnt = 0;
    for (int i = tid; i < BT; i += 1024) {
        if (label[i] != IGNORE_INDEX) {
            sum += g_per_token[i];
            cnt++;
        }
    }
    __shared__ float rs[1024];
    __shared__ int rc[1024];
    rs[tid] = sum; rc[tid] = cnt;
    __syncthreads();
    for (int s = 512; s > 0; s >>= 1) {
        if (tid < s) { rs[tid] += rs[tid + s]; rc[tid] += rc[tid + s]; }
        __syncthreads();
    }
    if (tid == 0) {
        int n = rc[0] > 1 ? rc[0] : 1;
        out[0] = rs[0] / (float)n;
    }
}

// ---------------- launch ----------------------------------------------------
extern "C" void kernel_launch(void* const* d_in, const int* in_sizes, int n_in,
                              void* d_out, int out_size)
{
    const float* s_in = (const float*)d_in[0];
    const float* s_w  = (const float*)d_in[1];
    const float* t_in = (const float*)d_in[2];
    const float* t_w  = (const float*)d_in[3];
    const int*   lab  = (const int*)d_in[4];
    float* out = (float*)d_out;

    // Not a stream API: safe outside AND inside graph capture; idempotent.
    cudaFuncSetAttribute(gemm_tc_kernel,
                         cudaFuncAttributeMaxDynamicSharedMemorySize, SMEM_DYN);

    // split fp32 -> [hi|hi|lo] / [hi|lo|hi] bf16 (dst bound device-side)
    split_kernel<<<2048, 256>>>(s_in, 0, HS, (long long)BT * HS);
    split_kernel<<<2048, 256>>>(t_in, 1, HT, (long long)BT * HT);
    split_kernel<<<8192, 256>>>(s_w, 2, HS, (long long)VSZ * HS);
    split_kernel<<<8192, 256>>>(t_w, 3, HT, (long long)VSZ * HT);

    dim3 grid(BT / 128, VSZ / 128);   // (16, 250), M-fastest for B reuse in L2
    gemm_tc_kernel<<<grid, 256, SMEM_DYN>>>(0);
    gemm_tc_kernel<<<grid, 256, SMEM_DYN>>>(1);

    rowstats_kernel<<<BT, 256>>>(1);
    rowstats_kernel<<<BT, 256>>>(0);
    jsd_kernel<<<BT, 256>>>();
    final_kernel<<<1, 1024>>>(lab, out);
}